// round 13
// baseline (speedup 1.0000x reference)
#include <cuda_runtime.h>
#include <cuda_bf16.h>
#include <cstdint>

// Problem constants
#define BATCH 64
#define CIN   64
#define H     128
#define W     128
#define HW    (H*W)
#define COUT  256
#define OH    126
#define OW    126
#define MTOT  (OH*OW)     // 15876
#define KTOT  (CIN*9)     // 576
#define NSTG  9           // 9 stages of K=64 (one per (kh,kw))

// Scratch (__device__ globals: allocation-free per harness rules)
// x in NHWC bf16: g_xn[b][h][w][ci]; +256 pad covers edge-row overreads (zero-init)
__device__ __align__(16) __nv_bfloat16 g_xn[(size_t)BATCH*H*W*CIN + 256];
// Weights transposed + K-reordered: g_wbf[k'][co], k' = (kh*3+kw)*64 + ci
__device__ __align__(16) __nv_bfloat16 g_wbf[KTOT*COUT];

// ---------------- prologue kernels ----------------

__global__ void cvt_nhwc_kernel(const float* __restrict__ x) {
    // one block per (h, b): transpose the [64c][128w] slice to [w][c] in bf16
    __shared__ __nv_bfloat16 tile[64 * 130];
    const int h = blockIdx.x, b = blockIdx.y, tid = threadIdx.x;
    #pragma unroll
    for (int i = 0; i < 32; i++) {
        int idx = tid + i * 256;           // 8192 elements
        int c = idx >> 7, w = idx & 127;
        tile[c * 130 + w] =
            __float2bfloat16(x[(((size_t)b * CIN + c) * H + h) * W + w]);
    }
    __syncthreads();
    __nv_bfloat16* dst = g_xn + (((size_t)b * H + h) * W) * CIN;
    #pragma unroll
    for (int i = 0; i < 32; i++) {
        int idx = tid + i * 256;
        int w = idx >> 6, c = idx & 63;
        dst[(size_t)w * CIN + c] = tile[c * 130 + w];
    }
}

// weights reorder + output zero in one launch
__global__ void cvt_w_zero_kernel(const float* __restrict__ w, float* __restrict__ out) {
    int kp = blockIdx.x;       // 0..575
    int n  = threadIdx.x;      // 0..255
    int ci  = kp & 63;
    int khw = kp >> 6;
    g_wbf[kp * COUT + n] = __float2bfloat16(w[n * KTOT + ci * 9 + khw]);
    if (kp < 64) out[kp * COUT + n] = 0.0f;    // 64*256 = BATCH*COUT
}

// ---------------- main implicit-GEMM kernel ----------------
// CTA tile: M128 (one oh row) x N128 (half of COUT); 4 warps, warp tile 64x64.
// A in smem as [m][k] rows of 64 ci (NHWC-native), non-trans ldmatrix.
// B in smem as [k][n], trans ldmatrix. K=64 stages; STG=3 ring; 2 CTAs/SM.

#define PA 144     // A smem row pitch BYTES (16B-aligned, conflict-free ldsm)
#define PN 136     // B smem pitch (elements)
#define STG 3
#define ASTG (128 * PA)      // 18432 B per K64 stage
#define BSTG (64 * PN * 2)   // 17408 B per K64 stage

__device__ __forceinline__ uint32_t smem_u32(const void* p) {
    return (uint32_t)__cvta_generic_to_shared(p);
}

__device__ __forceinline__ void cp16(uint32_t dst, const void* src) {
    asm volatile("cp.async.cg.shared.global [%0], [%1], 16;\n" :: "r"(dst), "l"(src));
}

__device__ __forceinline__ void ldsm4(uint32_t& r0, uint32_t& r1, uint32_t& r2,
                                      uint32_t& r3, uint32_t addr) {
    asm volatile("ldmatrix.sync.aligned.m8n8.x4.shared.b16 {%0,%1,%2,%3}, [%4];"
                 : "=r"(r0), "=r"(r1), "=r"(r2), "=r"(r3) : "r"(addr));
}

__device__ __forceinline__ void ldsm4t(uint32_t& r0, uint32_t& r1, uint32_t& r2,
                                       uint32_t& r3, uint32_t addr) {
    asm volatile("ldmatrix.sync.aligned.m8n8.x4.trans.shared.b16 {%0,%1,%2,%3}, [%4];"
                 : "=r"(r0), "=r"(r1), "=r"(r2), "=r"(r3) : "r"(addr));
}

__device__ __forceinline__ void mma16816(float c[4],
                                         uint32_t a0, uint32_t a1, uint32_t a2, uint32_t a3,
                                         uint32_t b0, uint32_t b1) {
    asm volatile("mma.sync.aligned.m16n8k16.row.col.f32.bf16.bf16.f32 "
                 "{%0,%1,%2,%3}, {%4,%5,%6,%7}, {%8,%9}, {%0,%1,%2,%3};"
                 : "+f"(c[0]), "+f"(c[1]), "+f"(c[2]), "+f"(c[3])
                 : "r"(a0), "r"(a1), "r"(a2), "r"(a3), "r"(b0), "r"(b1));
}

__device__ __forceinline__ float gelu_tanh(float x) {
    float x3 = x * x * x;
    float u = 0.7978845608028654f * fmaf(0.044715f, x3, x);
    float t;
    asm("tanh.approx.f32 %0, %1;" : "=f"(t) : "f"(u));
    return 0.5f * x * (1.0f + t);
}

__global__ void __launch_bounds__(128, 2)
conv_gemm_kernel(const float* __restrict__ bias, float* __restrict__ out) {
    extern __shared__ char dsm[];
    // Layout: A stages [STG][128*PA], then B stages [STG][64*PN*2]
    const uint32_t Abase = smem_u32(dsm);
    const uint32_t Bbase = Abase + STG * ASTG;

    const int tid    = threadIdx.x;
    const int lane   = tid & 31;
    const int warp   = tid >> 5;     // 0..3
    const int warp_m = warp >> 1;    // 0..1 -> 64 m-rows each
    const int warp_n = warp & 1;     // 0..1 -> 64 n-cols each
    const int oh = blockIdx.x;       // one output row per CTA
    const int n0 = blockIdx.y * 128; // COUT half
    const int b  = blockIdx.z;

    // B staging roles: thread handles k-rows (8i + sk), 16B chunk sj
    const int sk = tid >> 4, sj = tid & 15;

    const __nv_bfloat16* xb = g_xn + ((size_t)b * H) * W * CIN;
    const __nv_bfloat16* wsrc = g_wbf + n0 + sj * 8;   // + k'*COUT
    const uint32_t a_sdst = Abase + (uint32_t)tid * PA;
    const uint32_t b_sdst = Bbase + (sk * PN + sj * 8) * 2;

    // --- pipeline issue: one stage = K64 = one (kh,kw), ci 0..63 ---
    auto issue = [&](int st) {
        const int slot = st % STG;
        const int kh = (st * 11) >> 5;     // floor(st/3), st in [0,9)
        const int kw = st - kh * 3;
        // A: thread t copies its own m-row: 64 ci = 128B contiguous
        const __nv_bfloat16* asrc = xb + ((size_t)(oh + kh) * W + tid + kw) * CIN;
        const uint32_t ad = a_sdst + slot * ASTG;
        #pragma unroll
        for (int i = 0; i < 8; i++)
            cp16(ad + i * 16, asrc + i * 8);
        // B: k-rows 8i + sk
        const uint32_t bd = b_sdst + slot * BSTG;
        #pragma unroll
        for (int i = 0; i < 8; i++)
            cp16(bd + i * (8 * PN * 2), wsrc + (size_t)(st * 64 + i * 8 + sk) * COUT);
        asm volatile("cp.async.commit_group;" ::: "memory");
    };

    issue(0); issue(1);

    float acc[4][8][4];
    #pragma unroll
    for (int a = 0; a < 4; a++)
        #pragma unroll
        for (int c = 0; c < 8; c++)
            #pragma unroll
            for (int d = 0; d < 4; d++) acc[a][c][d] = 0.0f;

    // ldmatrix lane addressing (constant per lane)
    // A (non-trans): lane -> row (lane&15), k-half (lane>>4)
    const uint32_t a_loff = (uint32_t)((warp_m * 64 + (lane & 15)) * PA + (lane >> 4) * 16);
    // B (trans): as before
    const int b_krow = (lane & 7) + (lane & 8);
    const int b_noff = warp_n * 64 + ((lane & 16) >> 1);

    // double-buffered fragments (2 x 32 regs)
    uint32_t afr[2][4][4];
    uint32_t bfr[2][8][2];

    #pragma unroll
    for (int st = 0; st < NSTG; st++) {
        if (st < NSTG - 2) asm volatile("cp.async.wait_group 1;" ::: "memory");
        else               asm volatile("cp.async.wait_group 0;" ::: "memory");
        __syncthreads();

        const int slot = st % STG;
        const uint32_t a_base = Abase + slot * ASTG + a_loff;
        const uint32_t b_base = Bbase + slot * BSTG;

        // slice-0 fragments FIRST (tensor pipe restarts ASAP) ...
        #pragma unroll
        for (int mi = 0; mi < 4; mi++)
            ldsm4(afr[0][mi][0], afr[0][mi][1], afr[0][mi][2], afr[0][mi][3],
                  a_base + (uint32_t)(mi * 16 * PA));
        #pragma unroll
        for (int q = 0; q < 4; q++) {
            uint32_t addr = b_base + (uint32_t)((b_krow * PN + b_noff + q * 16) * 2);
            ldsm4t(bfr[0][2*q][0], bfr[0][2*q][1], bfr[0][2*q+1][0], bfr[0][2*q+1][1], addr);
        }
        // ... then the non-urgent cp.async for stage st+2 (slot (st+2)%3 != st%3)
        if (st + 2 < NSTG) issue(st + 2);

        // pipelined slices: ldsm(sl+1) before mma(sl); slice sl = k cols sl*16..+15
        #pragma unroll
        for (int sl = 0; sl < 4; sl++) {
            const int cur = sl & 1, nxt = cur ^ 1;
            if (sl < 3) {
                #pragma unroll
                for (int mi = 0; mi < 4; mi++)
                    ldsm4(afr[nxt][mi][0], afr[nxt][mi][1], afr[nxt][mi][2], afr[nxt][mi][3],
                          a_base + (uint32_t)(mi * 16 * PA + (sl + 1) * 32));
                #pragma unroll
                for (int q = 0; q < 4; q++) {
                    uint32_t addr = b_base +
                        (uint32_t)((((sl + 1) * 16 + b_krow) * PN + b_noff + q * 16) * 2);
                    ldsm4t(bfr[nxt][2*q][0], bfr[nxt][2*q][1],
                           bfr[nxt][2*q+1][0], bfr[nxt][2*q+1][1], addr);
                }
            }
            #pragma unroll
            for (int mi = 0; mi < 4; mi++)
                #pragma unroll
                for (int ni = 0; ni < 8; ni++)
                    mma16816(acc[mi][ni],
                             afr[cur][mi][0], afr[cur][mi][1],
                             afr[cur][mi][2], afr[cur][mi][3],
                             bfr[cur][ni][0], bfr[cur][ni][1]);
        }
    }

    // ---- epilogue: bias + GELU + row-mean partial reduction ----
    const int group = lane >> 2;
    const int tid4  = lane & 3;

    float bcol[16];
    #pragma unroll
    for (int j = 0; j < 16; j++) {
        int ni = j >> 1, bs = j & 1;
        bcol[j] = bias[n0 + warp_n * 64 + ni * 8 + tid4 * 2 + bs];
    }

    float csum[16];
    #pragma unroll
    for (int j = 0; j < 16; j++) csum[j] = 0.0f;

    #pragma unroll
    for (int mi = 0; mi < 4; mi++) {
        #pragma unroll
        for (int half = 0; half < 2; half++) {
            int ow = warp_m * 64 + mi * 16 + half * 8 + group;
            bool ok = (ow < OW);
            #pragma unroll
            for (int ni = 0; ni < 8; ni++) {
                #pragma unroll
                for (int bs = 0; bs < 2; bs++) {
                    if (ok) {
                        float y = acc[mi][ni][half * 2 + bs] + bcol[ni * 2 + bs];
                        csum[ni * 2 + bs] += gelu_tanh(y);
                    }
                }
            }
        }
    }

    // reduce over the 8 lane-groups holding the same columns
    #pragma unroll
    for (int j = 0; j < 16; j++) {
        csum[j] += __shfl_xor_sync(0xffffffffu, csum[j], 16);
        csum[j] += __shfl_xor_sync(0xffffffffu, csum[j], 8);
        csum[j] += __shfl_xor_sync(0xffffffffu, csum[j], 4);
    }

    if (lane < 4) {
        const float inv = 1.0f / (float)MTOT;
        #pragma unroll
        for (int j = 0; j < 16; j++) {
            int ni = j >> 1, bs = j & 1;
            int n = n0 + warp_n * 64 + ni * 8 + tid4 * 2 + bs;
            atomicAdd(&out[b * COUT + n], csum[j] * inv);
        }
    }
}

// ---------------- launch ----------------

#define DSMEM_BYTES (STG * (ASTG + BSTG))   // 107520

extern "C" void kernel_launch(void* const* d_in, const int* in_sizes, int n_in,
                              void* d_out, int out_size) {
    const float* x    = (const float*)d_in[0];   // [64,64,128,128]
    const float* w    = (const float*)d_in[1];   // [256,64,3,3]
    const float* bias = (const float*)d_in[2];   // [256]
    float* out = (float*)d_out;                  // [64,256]

    cudaFuncSetAttribute(conv_gemm_kernel,
                         cudaFuncAttributeMaxDynamicSharedMemorySize, DSMEM_BYTES);

    // 1) x -> NHWC bf16 (single copy; kw shift is a 128B-aligned offset now)
    cvt_nhwc_kernel<<<dim3(H, BATCH), 256>>>(x);
    // 2) weights -> bf16 K-reordered [k'][co]; zero output accumulator
    cvt_w_zero_kernel<<<KTOT, COUT>>>(w, out);
    // 3) fused implicit-GEMM conv + bias + GELU + mean-pool
    dim3 grid(OH, 2, BATCH);    // (126, 2 n-halves, 64)
    conv_gemm_kernel<<<grid, 128, DSMEM_BYTES>>>(bias, out);
}